// round 10
// baseline (speedup 1.0000x reference)
#include <cuda_runtime.h>

#define NN 512
#define CC 16
#define LTL 3
#define AGG_IN 1028
#define TPB 128
#define TILE 128
#define NTILES ((NN * NN) / TILE)   // 2048
#define NCHUNK 4                    // 128-edge chunks per q
#define GRIDX 304                   // 2 CTAs per SM (152 SMs on GB300)
#define ST_F4 2944                  // float4 per stage: 640 svW + 640 svb + 1664 sw1
#define SMEM_BYTES (2 * ST_F4 * 16) // 94208 B (double buffer)

// scratch (no allocation allowed)
__device__ float g_part[NN * 3 * NCHUNK];
__device__ unsigned g_cnt[NN];
__device__ float g_act[2][NN];

__device__ __forceinline__ float tanh_e(float x) {
    x = fminf(fmaxf(x, -15.0f), 15.0f);
    float e = __expf(2.0f * x);
    return __fdividef(e - 1.0f, e + 1.0f);
}

__device__ __forceinline__ void cp_async16(void* smem_dst, const void* gsrc) {
    unsigned s = (unsigned)__cvta_generic_to_shared(smem_dst);
    asm volatile("cp.async.cg.shared.global [%0], [%1], 16;\n" :: "r"(s), "l"(gsrc));
}

// per-tile scalar operands kept in registers (explicit cur/nxt pair, no dyn idx)
struct Small {
    float ap, b1x, b1y, b1z, w2x, w2y, w2z, b2, aw0, aw1, aw2;   // all threads
    float oh0, oh1, oh2, e10, e11, e12, w20, w21, w22, eb2;      // thread 0 only
};

// ---------------------------------------------------------------------------
// Persistent double-buffered edge kernel. Each CTA owns ~7 tiles of 128 edges;
// cp.async stages tile i+1 while tile i computes -> DRAM never idles.
// Access pattern identical to R8 (coalesced staging, padded conflict-free smem).
// ---------------------------------------------------------------------------
__global__ __launch_bounds__(TPB) void edge_kernel(
    const float* __restrict__ a_ext, int in_buf, int out_buf, int l,
    float* __restrict__ dout,
    const float* __restrict__ vW,  const float* __restrict__ vb,
    const float* __restrict__ sW1, const float* __restrict__ sb1,
    const float* __restrict__ sW2, const float* __restrict__ sb2,
    const float* __restrict__ aW1, const float* __restrict__ ab1,
    const float* __restrict__ aW2, const float* __restrict__ ab2)
{
    extern __shared__ float4 smem[];
    __shared__ float red[3][TPB / 32];

    const int t = threadIdx.x;
    const float* a_in = a_ext ? a_ext : g_act[in_buf];

    // --- stage tile tau into smem buffer s (coalesced cp.async) ---
    auto stage = [&](int tau, int s) {
        const size_t e0 = (size_t)tau * TILE;
        const float4* gvW = (const float4*)(vW  + e0 * CC);
        const float4* gvb = (const float4*)(vb  + e0 * CC);
        const float4* gs1 = (const float4*)(sW1 + e0 * 48);
        float4* bW = smem + s * ST_F4;
        float4* bB = bW + 640;
        float4* b1 = bW + 1280;
        #pragma unroll
        for (int r = 0; r < 4; ++r) {
            int i = t + r * TPB;
            cp_async16(&bW[(i >> 2) * 5 + (i & 3)], &gvW[i]);
        }
        #pragma unroll
        for (int r = 0; r < 4; ++r) {
            int i = t + r * TPB;
            cp_async16(&bB[(i >> 2) * 5 + (i & 3)], &gvb[i]);
        }
        #pragma unroll
        for (int r = 0; r < 12; ++r) {
            int i = t + r * TPB;
            int e = i / 12;
            cp_async16(&b1[e * 13 + (i - e * 12)], &gs1[i]);
        }
    };

    // --- prefetch per-tile scalars into registers ---
    auto fetch_small = [&](int tau) -> Small {
        Small sm;
        const size_t e = (size_t)tau * TILE + t;
        const int q = tau >> 2;
        const int p = ((tau & 3) << 7) + t;
        sm.ap  = __ldg(&a_in[p]);
        sm.b1x = __ldg(&sb1[e * 3 + 0]);
        sm.b1y = __ldg(&sb1[e * 3 + 1]);
        sm.b1z = __ldg(&sb1[e * 3 + 2]);
        sm.w2x = __ldg(&sW2[e * 3 + 0]);
        sm.w2y = __ldg(&sW2[e * 3 + 1]);
        sm.w2z = __ldg(&sW2[e * 3 + 2]);
        sm.b2  = __ldg(&sb2[e]);
        sm.aw0 = __ldg(&aW1[((size_t)q * 3 + 0) * AGG_IN + p]);
        sm.aw1 = __ldg(&aW1[((size_t)q * 3 + 1) * AGG_IN + p]);
        sm.aw2 = __ldg(&aW1[((size_t)q * 3 + 2) * AGG_IN + p]);
        if (t == 0) {   // epilogue operands (one-hots, biases, fc2 weights)
            const float* r0 = aW1 + ((size_t)q * 3 + 0) * AGG_IN;
            const float* r1 = aW1 + ((size_t)q * 3 + 1) * AGG_IN;
            const float* r2 = aW1 + ((size_t)q * 3 + 2) * AGG_IN;
            sm.oh0 = __ldg(&r0[NN + l + 1]) + __ldg(&r0[NN + 4 + q]);
            sm.oh1 = __ldg(&r1[NN + l + 1]) + __ldg(&r1[NN + 4 + q]);
            sm.oh2 = __ldg(&r2[NN + l + 1]) + __ldg(&r2[NN + 4 + q]);
            sm.e10 = __ldg(&ab1[q * 3 + 0]);
            sm.e11 = __ldg(&ab1[q * 3 + 1]);
            sm.e12 = __ldg(&ab1[q * 3 + 2]);
            sm.w20 = __ldg(&aW2[q * 3 + 0]);
            sm.w21 = __ldg(&aW2[q * 3 + 1]);
            sm.w22 = __ldg(&aW2[q * 3 + 2]);
            sm.eb2 = __ldg(&ab2[q]);
        }
        return sm;
    };

    // --- pipeline prologue: stage first tile ---
    int tau = blockIdx.x;            // < NTILES always (304 < 2048)
    stage(tau, 0);
    Small cur = fetch_small(tau);
    asm volatile("cp.async.commit_group;\n" ::: "memory");

    Small nxt;
    for (int i = 0; tau < NTILES; tau += GRIDX, ++i) {
        const int buf = i & 1;
        const int ntau = tau + GRIDX;
        const bool have_next = (ntau < NTILES);
        if (have_next) {
            stage(ntau, buf ^ 1);
            nxt = fetch_small(ntau);
        }
        asm volatile("cp.async.commit_group;\n" ::: "memory");
        if (have_next) asm volatile("cp.async.wait_group 1;\n" ::: "memory");
        else           asm volatile("cp.async.wait_group 0;\n" ::: "memory");
        __syncthreads();

        // ---- compute tile tau from buffer buf ----
        const float4* bW = smem + buf * ST_F4;
        const float4* bB = bW + 640;
        const float4* b1 = bW + 1280;

        float f[16];
        #pragma unroll
        for (int g = 0; g < 4; ++g) {
            float4 w = bW[t * 5 + g];
            float4 b = bB[t * 5 + g];
            f[4*g+0] = tanh_e(fmaf(cur.ap, w.x, b.x));
            f[4*g+1] = tanh_e(fmaf(cur.ap, w.y, b.y));
            f[4*g+2] = tanh_e(fmaf(cur.ap, w.z, b.z));
            f[4*g+3] = tanh_e(fmaf(cur.ap, w.w, b.w));
        }

        float h1[3];
        const float bb1[3] = {cur.b1x, cur.b1y, cur.b1z};
        #pragma unroll
        for (int o = 0; o < 3; ++o) {
            float acc = bb1[o];
            #pragma unroll
            for (int g = 0; g < 4; ++g) {
                float4 w = b1[t * 13 + o * 4 + g];
                acc = fmaf(w.x, f[4*g+0], acc);
                acc = fmaf(w.y, f[4*g+1], acc);
                acc = fmaf(w.z, f[4*g+2], acc);
                acc = fmaf(w.w, f[4*g+3], acc);
            }
            h1[o] = tanh_e(acc);
        }
        float sv = cur.b2;
        sv = fmaf(cur.w2x, h1[0], sv);
        sv = fmaf(cur.w2y, h1[1], sv);
        sv = fmaf(cur.w2z, h1[2], sv);
        const float s = tanh_e(sv);

        // fused aggregator partials over this 128-edge chunk
        float pk[3] = {cur.aw0 * s, cur.aw1 * s, cur.aw2 * s};
        #pragma unroll
        for (int off = 16; off > 0; off >>= 1) {
            pk[0] += __shfl_down_sync(0xffffffffu, pk[0], off);
            pk[1] += __shfl_down_sync(0xffffffffu, pk[1], off);
            pk[2] += __shfl_down_sync(0xffffffffu, pk[2], off);
        }
        if ((t & 31) == 0) {
            const int w = t >> 5;
            red[0][w] = pk[0];
            red[1][w] = pk[1];
            red[2][w] = pk[2];
        }
        __syncthreads();

        if (t == 0) {
            const int q = tau >> 2;
            const int chunk = tau & 3;
            #pragma unroll
            for (int k = 0; k < 3; ++k)
                g_part[(q * 3 + k) * NCHUNK + chunk] =
                    red[k][0] + red[k][1] + red[k][2] + red[k][3];
            __threadfence();
            unsigned old = atomicAdd(&g_cnt[q], 1u);
            if (old == NCHUNK - 1u) {       // last chunk of q: epilogue
                __threadfence();            // acquire other CTAs' g_part
                const float* gp = &g_part[q * 3 * NCHUNK];
                float t0 = cur.oh0 + cur.e10, t1 = cur.oh1 + cur.e11, t2 = cur.oh2 + cur.e12;
                #pragma unroll
                for (int c = 0; c < NCHUNK; ++c) {
                    t0 += gp[0 * NCHUNK + c];
                    t1 += gp[1 * NCHUNK + c];
                    t2 += gp[2 * NCHUNK + c];
                }
                float out = cur.eb2;
                out = fmaf(cur.w20, tanh_e(t0), out);
                out = fmaf(cur.w21, tanh_e(t1), out);
                out = fmaf(cur.w22, tanh_e(t2), out);
                if (dout) dout[NN - 1 - q] = out;   // final layer: reversed
                else      g_act[out_buf][q] = out;
                g_cnt[q] = 0u;                      // reset for next layer/replay
            }
        }
        cur = nxt;   // register moves; garbage on last iter (unused)
    }
}

extern "C" void kernel_launch(void* const* d_in, const int* in_sizes, int n_in,
                              void* d_out, int out_size)
{
    const float* x      = (const float*)d_in[0];
    const float* vec_W  = (const float*)d_in[1];
    const float* vec_b  = (const float*)d_in[2];
    const float* syn_W1 = (const float*)d_in[3];
    const float* syn_b1 = (const float*)d_in[4];
    const float* syn_W2 = (const float*)d_in[5];
    const float* syn_b2 = (const float*)d_in[6];
    const float* agg_W1 = (const float*)d_in[7];
    const float* agg_b1 = (const float*)d_in[8];
    const float* agg_W2 = (const float*)d_in[9];
    const float* agg_b2 = (const float*)d_in[10];
    float* out = (float*)d_out;

    cudaFuncSetAttribute(edge_kernel,
                         cudaFuncAttributeMaxDynamicSharedMemorySize, SMEM_BYTES);

    const size_t VEC_L = (size_t)NN * NN * CC;
    const size_t SW1_L = (size_t)NN * NN * 48;
    const size_t SB1_L = (size_t)NN * NN * 3;
    const size_t SB2_L = (size_t)NN * NN;
    const size_t AW1_L = (size_t)NN * 3 * AGG_IN;
    const size_t AB1_L = (size_t)NN * 3;   // stride for agg_b1 AND agg_W2
    const size_t AB2_L = (size_t)NN;       // stride for agg_b2

    for (int l = 0; l < LTL; ++l) {
        const float* a_ext = (l == 0) ? x : nullptr;
        const int in_buf  = (l == 1) ? 0 : 1;
        const int out_buf = (l == 0) ? 0 : 1;
        float* dw = (l == LTL - 1) ? out : nullptr;

        edge_kernel<<<GRIDX, TPB, SMEM_BYTES>>>(
            a_ext, in_buf, out_buf, l, dw,
            vec_W  + (size_t)l * VEC_L,  vec_b  + (size_t)l * VEC_L,
            syn_W1 + (size_t)l * SW1_L,  syn_b1 + (size_t)l * SB1_L,
            syn_W2 + (size_t)l * SB1_L,  syn_b2 + (size_t)l * SB2_L,
            agg_W1 + (size_t)l * AW1_L,  agg_b1 + (size_t)l * AB1_L,
            agg_W2 + (size_t)l * AB1_L,  agg_b2 + (size_t)l * AB2_L);
    }
}

// round 11
// speedup vs baseline: 1.4722x; 1.4722x over previous
#include <cuda_runtime.h>

#define NN 512
#define CC 16
#define LTL 3
#define AGG_IN 1028
#define EPC 64             // edges per CTA
#define TPB 64
#define NCHUNK 8           // chunks per q

// scratch (no allocation allowed)
__device__ float g_part[NN * 3 * NCHUNK];  // per-(q,k,chunk) aggregator partials
__device__ unsigned g_cnt[NN];             // arrival counters (self-resetting)
__device__ float g_act[2][NN];             // ping-pong activations

__device__ __forceinline__ float tanh_e(float x) {
    x = fminf(fmaxf(x, -15.0f), 15.0f);
    float e = __expf(2.0f * x);
    return __fdividef(e - 1.0f, e + 1.0f);
}

__device__ __forceinline__ void cp_async16(void* smem_dst, const void* gsrc) {
    unsigned s = (unsigned)__cvta_generic_to_shared(smem_dst);
    asm volatile("cp.async.cg.shared.global [%0], [%1], 16;\n" :: "r"(s), "l"(gsrc));
}

// ---------------------------------------------------------------------------
// Edge kernel, 64 edges/CTA (R8 architecture) + split-commit overlap:
//   group A = vW/vb staging, group B = sW1 staging.
//   After wait(A): compute all 16 VEC tanh's WHILE B is still in flight.
//   After wait(B): synapse + fused aggregator partials + epilogue.
// This hides the MUFU-heavy VEC phase under sW1's DRAM fetch, raising the
// per-CTA DRAM duty cycle (the R7-R10 limiter).
// ---------------------------------------------------------------------------
__global__ __launch_bounds__(TPB) void edge_kernel(
    const float* __restrict__ a_ext, int in_buf, int out_buf, int l,
    float* __restrict__ dout,
    const float* __restrict__ vW,  const float* __restrict__ vb,
    const float* __restrict__ sW1, const float* __restrict__ sb1,
    const float* __restrict__ sW2, const float* __restrict__ sb2,
    const float* __restrict__ aW1, const float* __restrict__ ab1,
    const float* __restrict__ aW2, const float* __restrict__ ab2)
{
    __shared__ float4 svW[EPC * 5];    // padded: 5 granules per edge (4 used)
    __shared__ float4 svb[EPC * 5];
    __shared__ float4 sw1[EPC * 13];   // padded: 13 granules per edge (12 used)
    __shared__ float red[3][2];

    const int t   = threadIdx.x;
    const int cta = blockIdx.x;
    const size_t e0 = (size_t)cta * EPC;
    const int q     = cta >> 3;
    const int chunk = cta & 7;
    const int p     = (chunk << 6) + t;
    const size_t eg = e0 + t;

    // --- group A: vW + vb (needed first, by the VEC phase) ---
    const float4* gvW = (const float4*)(vW  + e0 * CC);
    const float4* gvb = (const float4*)(vb  + e0 * CC);
    #pragma unroll
    for (int r = 0; r < 4; ++r) {
        int i = t + r * TPB;
        cp_async16(&svW[(i >> 2) * 5 + (i & 3)], &gvW[i]);
    }
    #pragma unroll
    for (int r = 0; r < 4; ++r) {
        int i = t + r * TPB;
        cp_async16(&svb[(i >> 2) * 5 + (i & 3)], &gvb[i]);
    }
    asm volatile("cp.async.commit_group;\n" ::: "memory");

    // --- group B: sW1 (needed later, by the synapse phase) ---
    const float4* gs1 = (const float4*)(sW1 + e0 * 48);
    #pragma unroll
    for (int r = 0; r < 12; ++r) {
        int i = t + r * TPB;
        int e = i / 12;
        cp_async16(&sw1[e * 13 + (i - e * 12)], &gs1[i]);
    }
    asm volatile("cp.async.commit_group;\n" ::: "memory");

    // --- small direct loads (overlap with both async groups) ---
    const float* a_in = a_ext ? a_ext : g_act[in_buf];
    const float ap = __ldg(&a_in[p]);
    const float b1_0 = __ldg(&sb1[eg * 3 + 0]);
    const float b1_1 = __ldg(&sb1[eg * 3 + 1]);
    const float b1_2 = __ldg(&sb1[eg * 3 + 2]);
    const float w2_0 = __ldg(&sW2[eg * 3 + 0]);
    const float w2_1 = __ldg(&sW2[eg * 3 + 1]);
    const float w2_2 = __ldg(&sW2[eg * 3 + 2]);
    const float b2   = __ldg(&sb2[eg]);
    float aw[3];
    #pragma unroll
    for (int k = 0; k < 3; ++k)
        aw[k] = __ldg(&aW1[((size_t)q * 3 + k) * AGG_IN + p]);

    // --- epilogue prefetch (thread 0 only; hidden under the stream) ---
    float oh[3], eb1[3], ew2[3], eb2 = 0.f;
    if (t == 0) {
        #pragma unroll
        for (int k = 0; k < 3; ++k) {
            const float* row = aW1 + ((size_t)q * 3 + k) * AGG_IN;
            oh[k]  = __ldg(&row[NN + l + 1]) + __ldg(&row[NN + 4 + q]); // one-hots
            eb1[k] = __ldg(&ab1[q * 3 + k]);
            ew2[k] = __ldg(&aW2[q * 3 + k]);
        }
        eb2 = __ldg(&ab2[q]);
    }

    // --- wait for group A only; B (sW1) still streaming from DRAM ---
    asm volatile("cp.async.wait_group 1;\n" ::: "memory");
    __syncthreads();

    // --- VEC: f[c] = tanh(ap*vW[c] + vb[c]) --- (overlaps sW1 fetch)
    float f[16];
    #pragma unroll
    for (int g = 0; g < 4; ++g) {
        float4 w = svW[t * 5 + g];
        float4 b = svb[t * 5 + g];
        f[4*g+0] = tanh_e(fmaf(ap, w.x, b.x));
        f[4*g+1] = tanh_e(fmaf(ap, w.y, b.y));
        f[4*g+2] = tanh_e(fmaf(ap, w.z, b.z));
        f[4*g+3] = tanh_e(fmaf(ap, w.w, b.w));
    }

    // --- now require sW1 ---
    asm volatile("cp.async.wait_group 0;\n" ::: "memory");
    __syncthreads();

    // --- Synapse: Linear(16->3) -> tanh -> Linear(3->1) -> tanh ---
    float h1[3];
    const float bb1[3] = {b1_0, b1_1, b1_2};
    #pragma unroll
    for (int o = 0; o < 3; ++o) {
        float acc = bb1[o];
        #pragma unroll
        for (int g = 0; g < 4; ++g) {
            float4 w = sw1[t * 13 + o * 4 + g];
            acc = fmaf(w.x, f[4*g+0], acc);
            acc = fmaf(w.y, f[4*g+1], acc);
            acc = fmaf(w.z, f[4*g+2], acc);
            acc = fmaf(w.w, f[4*g+3], acc);
        }
        h1[o] = tanh_e(acc);
    }
    float sv = b2;
    sv = fmaf(w2_0, h1[0], sv);
    sv = fmaf(w2_1, h1[1], sv);
    sv = fmaf(w2_2, h1[2], sv);
    const float s = tanh_e(sv);

    // --- fused aggregator partials: sum_p aW1[q,k,p]*s_p over this chunk ---
    float pk[3] = {aw[0] * s, aw[1] * s, aw[2] * s};
    #pragma unroll
    for (int off = 16; off > 0; off >>= 1) {
        pk[0] += __shfl_down_sync(0xffffffffu, pk[0], off);
        pk[1] += __shfl_down_sync(0xffffffffu, pk[1], off);
        pk[2] += __shfl_down_sync(0xffffffffu, pk[2], off);
    }
    if ((t & 31) == 0) {
        const int w = t >> 5;
        red[0][w] = pk[0];
        red[1][w] = pk[1];
        red[2][w] = pk[2];
    }
    __syncthreads();

    if (t == 0) {
        // single thread writes all 3 partials -> one fence orders them all
        #pragma unroll
        for (int k = 0; k < 3; ++k)
            g_part[(q * 3 + k) * NCHUNK + chunk] = red[k][0] + red[k][1];
        __threadfence();
        unsigned old = atomicAdd(&g_cnt[q], 1u);
        if (old == NCHUNK - 1u) {   // last CTA for this q: epilogue
            __threadfence();        // acquire: see other CTAs' g_part writes
            float out = eb2;
            #pragma unroll
            for (int k = 0; k < 3; ++k) {
                const float* gp = &g_part[(q * 3 + k) * NCHUNK];
                float tot = oh[k] + eb1[k];
                #pragma unroll
                for (int c = 0; c < NCHUNK; ++c) tot += gp[c];
                out = fmaf(ew2[k], tanh_e(tot), out);
            }
            if (dout) dout[NN - 1 - q] = out;   // final layer: reversed
            else      g_act[out_buf][q] = out;
            g_cnt[q] = 0u;                      // reset for next layer / replay
        }
    }
}

extern "C" void kernel_launch(void* const* d_in, const int* in_sizes, int n_in,
                              void* d_out, int out_size)
{
    const float* x      = (const float*)d_in[0];
    const float* vec_W  = (const float*)d_in[1];
    const float* vec_b  = (const float*)d_in[2];
    const float* syn_W1 = (const float*)d_in[3];
    const float* syn_b1 = (const float*)d_in[4];
    const float* syn_W2 = (const float*)d_in[5];
    const float* syn_b2 = (const float*)d_in[6];
    const float* agg_W1 = (const float*)d_in[7];
    const float* agg_b1 = (const float*)d_in[8];
    const float* agg_W2 = (const float*)d_in[9];
    const float* agg_b2 = (const float*)d_in[10];
    float* out = (float*)d_out;

    const size_t VEC_L = (size_t)NN * NN * CC;
    const size_t SW1_L = (size_t)NN * NN * 48;
    const size_t SB1_L = (size_t)NN * NN * 3;
    const size_t SB2_L = (size_t)NN * NN;
    const size_t AW1_L = (size_t)NN * 3 * AGG_IN;
    const size_t AB1_L = (size_t)NN * 3;   // stride for agg_b1 AND agg_W2 (both (LT,N,3))
    const size_t AB2_L = (size_t)NN;       // stride for agg_b2 (LT,N)

    const int NCTA = (NN * NN) / EPC;   // 4096

    for (int l = 0; l < LTL; ++l) {
        const float* a_ext = (l == 0) ? x : nullptr;
        const int in_buf  = (l == 1) ? 0 : 1;
        const int out_buf = (l == 0) ? 0 : 1;
        float* dw = (l == LTL - 1) ? out : nullptr;

        edge_kernel<<<NCTA, TPB>>>(
            a_ext, in_buf, out_buf, l, dw,
            vec_W  + (size_t)l * VEC_L,  vec_b  + (size_t)l * VEC_L,
            syn_W1 + (size_t)l * SW1_L,  syn_b1 + (size_t)l * SB1_L,
            syn_W2 + (size_t)l * SB1_L,  syn_b2 + (size_t)l * SB2_L,
            agg_W1 + (size_t)l * AW1_L,  agg_b1 + (size_t)l * AB1_L,
            agg_W2 + (size_t)l * AB1_L,  agg_b2 + (size_t)l * AB2_L);
    }
}